// round 6
// baseline (speedup 1.0000x reference)
#include <cuda_runtime.h>
#include <stdint.h>

#define N_OBJ 16384
#define N_DIM 4096
#define INV_SQRT2 0.70710678118654752440f

// Compacted valid bins per dim (capacity N_OBJ each) + per-dim counts.
__device__ uint16_t g_comp[(size_t)N_DIM * N_OBJ];
__device__ uint32_t g_cnt[N_DIM];

// thr(j) = 0.05f * float32((j+1)/16384)
__device__ __forceinline__ float thr(int j) {
    return __fmul_rn(0.05f, (float)(j + 1) * 6.103515625e-05f);
}

__global__ void zero_cnt_kernel() {
    int i = blockIdx.x * 1024 + threadIdx.x;
    if (i < N_DIM) g_cnt[i] = 0;
}

// ---------------- phase 1: arithmetic bins + warp-ballot compaction -------
// Block 256 = (32 tx=dim, 8 ty=obj), 8 objs/thread -> tile 32 dims x 64 objs.
#define P1_THREADS 256

__global__ void __launch_bounds__(P1_THREADS) phase1_kernel(
        const float* __restrict__ q_mu, const float* __restrict__ q_var) {
    __shared__ uint16_t s_tile[32 * 66];            // [dim][obj], padded

    const int tid = threadIdx.x, tx = tid & 31, ty = tid >> 5;
    const int dt = blockIdx.x;                       // dim tile (0..127)
    const int ot = blockIdx.y;                       // obj tile (0..255), 64 objs
    const size_t base = (size_t)(ot * 64 + ty) * N_DIM + dt * 32 + tx;

    float mm[8], vv[8];
    #pragma unroll
    for (int r = 0; r < 8; r++) {
        mm[r] = q_mu[base + (size_t)(r * 8) * N_DIM];
        vv[r] = q_var[base + (size_t)(r * 8) * N_DIM];
    }

    #pragma unroll
    for (int r = 0; r < 8; r++) {
        // p = 0.5*erfc(x), x = (mu/v)/sqrt2. Clamp x>=1: p(1)=0.0786 > 0.05,
        // so clamped values land in the sentinel region regardless.
        float x = __fdividef(mm[r], vv[r]) * INV_SQRT2;
        float xc = fmaxf(x, 1.0f);

        float h = xc * xc;                  // exp(-x^2), Dekker-corrected
        float l = fmaf(xc, xc, -h);
        float e = __expf(-h);
        e = fmaf(-l, e, e);

        float den = fmaf(0.3275911f, xc, 1.0f);      // A&S 7.1.26, err<=1.5e-7
        float t = __fdividef(1.0f, den);
        float poly = fmaf(t, 1.061405429f, -1.453152027f);
        poly = fmaf(t, poly, 1.421413741f);
        poly = fmaf(t, poly, -0.284496736f);
        poly = fmaf(t, poly, 0.254829592f);
        float p = 0.5f * t * poly * e;

        uint16_t bin = 0xFFFFu;
        if (p <= 0.05f) {                            // thr(16383) == 0.05f
            int j = (int)ceilf(p * 327680.0f) - 1;   // thresholds uniform in p
            j = min(max(j, 0), N_OBJ - 1);
            while (j > 0 && p <= thr(j - 1)) --j;    // fp fixup, ~0-1 iters
            while (j < N_OBJ - 1 && p > thr(j)) ++j;
            bin = (uint16_t)j;
        }
        s_tile[tx * 66 + (ty + r * 8)] = bin;
    }
    __syncthreads();

    // Warp-ballot compaction: warp w handles dims {w, w+8, w+16, w+24}.
    // One atomicAdd per (warp, dim) reserves a slot range; valid lanes write
    // rank-ordered, contiguous u16 (coalesced runs). Row order is
    // nondeterministic but the histogram consumer is order-invariant.
    const int lane = tid & 31, wrp = tid >> 5;
    for (int dd = wrp; dd < 32; dd += 8) {
        const int d = dt * 32 + dd;
        uint16_t v0 = s_tile[dd * 66 + lane];
        uint16_t v1 = s_tile[dd * 66 + 32 + lane];
        unsigned m0 = __ballot_sync(0xffffffffu, v0 != 0xFFFFu);
        unsigned m1 = __ballot_sync(0xffffffffu, v1 != 0xFFFFu);
        int n0 = __popc(m0), n1 = __popc(m1);
        uint32_t off = 0;
        if (lane == 0 && (n0 + n1)) off = atomicAdd(&g_cnt[d], (uint32_t)(n0 + n1));
        off = __shfl_sync(0xffffffffu, off, 0);
        uint16_t* dst = g_comp + (size_t)d * N_OBJ + off;
        unsigned lt = (1u << lane) - 1u;
        if (v0 != 0xFFFFu) dst[__popc(m0 & lt)] = v0;
        if (v1 != 0xFFFFu) dst[n0 + __popc(m1 & lt)] = v1;
    }
}

// ---------------- phase 2: dense histogram of compacted row + scan --------
__global__ __launch_bounds__(1024, 2) void phase2_kernel(float* __restrict__ out) {
    extern __shared__ uint32_t hist[];       // up to 16384 u32 = 64 KB
    __shared__ uint32_t warp_part[32];
    __shared__ uint32_t s_carry;
    __shared__ uint32_t red_cnt[32];
    __shared__ int      red_min[32];

    const int tid = threadIdx.x, lane = tid & 31, wid = tid >> 5;
    const int d = blockIdx.x;

    const uint32_t C = g_cnt[d];
    if (C == 0) { if (tid == 0) out[d] = 0.0f; return; }
    const int chunks = min(16, (int)((C + 1023u) >> 10));
    const uint32_t limit = (uint32_t)chunks << 10;

    {   // vectorized zero of hist[0..limit)
        uint4* h4 = (uint4*)hist;
        uint4 z4 = {0u, 0u, 0u, 0u};
        for (int k = tid; k < (int)(limit >> 2); k += 1024) h4[k] = z4;
    }
    if (tid == 0) s_carry = 0;
    __syncthreads();

    // Dense histogram over C compacted values (~C/8192 iterations).
    // k is always a multiple of 8 so uint4 loads stay in-row and aligned.
    const uint16_t* row = g_comp + (size_t)d * N_OBJ;
    uint32_t zc = 0;                          // bin 0 hot -> warp-aggregate
    for (uint32_t k = (uint32_t)tid * 8; k < C; k += 8192) {
        uint4 v = *(const uint4*)(row + k);
        uint32_t ww[4] = {v.x, v.y, v.z, v.w};
        #pragma unroll
        for (int e = 0; e < 8; e++) {
            uint32_t b = (e & 1) ? (ww[e >> 1] >> 16) : (ww[e >> 1] & 0xFFFFu);
            if (k + e < C) {
                if (b == 0u) zc++;
                else if (b < limit) atomicAdd(&hist[b], 1u);
            }
        }
    }
    #pragma unroll
    for (int o = 16; o > 0; o >>= 1) zc += __shfl_down_sync(0xffffffffu, zc, o);
    if (lane == 0 && zc) atomicAdd(&hist[0], zc);
    __syncthreads();

    // chunked inclusive scan over [0, limit): reject[j] = cum(j) >= j+1
    uint32_t count = 0;
    int firstj = 0x7fffffff;
    for (int c = 0; c < chunks; ++c) {
        int j = c * 1024 + tid;
        uint32_t x = hist[j];
        #pragma unroll
        for (int o = 1; o < 32; o <<= 1) {
            uint32_t y = __shfl_up_sync(0xffffffffu, x, o);
            if (lane >= o) x += y;
        }
        if (lane == 31) warp_part[wid] = x;
        __syncthreads();
        if (wid == 0) {
            uint32_t ww = warp_part[lane];
            #pragma unroll
            for (int o = 1; o < 32; o <<= 1) {
                uint32_t y = __shfl_up_sync(0xffffffffu, ww, o);
                if (lane >= o) ww += y;
            }
            warp_part[lane] = ww;
        }
        __syncthreads();
        uint32_t incl = x + (wid > 0 ? warp_part[wid - 1] : 0u) + s_carry;
        if (incl >= (uint32_t)(j + 1)) { count++; firstj = min(firstj, j); }
        __syncthreads();
        if (tid == 0) s_carry += warp_part[31];
        __syncthreads();
    }

    #pragma unroll
    for (int o = 16; o > 0; o >>= 1) {
        count += __shfl_down_sync(0xffffffffu, count, o);
        firstj = min(firstj, __shfl_down_sync(0xffffffffu, firstj, o));
    }
    if (lane == 0) { red_cnt[wid] = count; red_min[wid] = firstj; }
    __syncthreads();
    if (wid == 0) {
        uint32_t cc = red_cnt[lane];
        int mm = red_min[lane];
        #pragma unroll
        for (int o = 16; o > 0; o >>= 1) {
            cc += __shfl_down_sync(0xffffffffu, cc, o);
            mm = min(mm, __shfl_down_sync(0xffffffffu, mm, o));
        }
        if (lane == 0) {
            uint32_t imp = cc + ((mm == 0x7fffffff) ? 0u : (uint32_t)mm);
            out[d] = (float)imp;
        }
    }
}

extern "C" void kernel_launch(void* const* d_in, const int* in_sizes, int n_in,
                              void* d_out, int out_size) {
    const float* q_mu  = (const float*)d_in[0];
    const float* q_var = (const float*)d_in[1];
    float* out = (float*)d_out;

    cudaFuncSetAttribute((const void*)phase2_kernel,
                         cudaFuncAttributeMaxDynamicSharedMemorySize,
                         N_OBJ * (int)sizeof(uint32_t));

    zero_cnt_kernel<<<N_DIM / 1024, 1024>>>();
    dim3 g1(N_DIM / 32, N_OBJ / 64);
    phase1_kernel<<<g1, P1_THREADS>>>(q_mu, q_var);
    phase2_kernel<<<N_DIM, 1024, N_OBJ * sizeof(uint32_t)>>>(out);
}

// round 8
// speedup vs baseline: 1.3438x; 1.3438x over previous
#include <cuda_runtime.h>
#include <stdint.h>

#define N_OBJ 16384
#define N_DIM 4096
#define OTILES 256              // 64-obj segments per dim row
#define SENT 0xFFFFu
#define INV_SQRT2 0.70710678118654752440f

// Segmented-compact bins: segment (d, ot) = g_bins[d*N_OBJ + ot*64 ...], first
// g_tcnt[d*OTILES+ot] entries valid (rank-packed), rest garbage (never read).
__device__ uint16_t g_bins[(size_t)N_DIM * N_OBJ];
__device__ uint8_t  g_tcnt[N_DIM * OTILES];

// thr(j) = 0.05f * float32((j+1)/16384)
__device__ __forceinline__ float thr(int j) {
    return __fmul_rn(0.05f, (float)(j + 1) * 6.103515625e-05f);
}

// ---------------- phase 1: arithmetic bins + deterministic segment pack ---
// Block 256 = (32 tx=dim, 8 ty=obj), 8 objs/thread -> tile 32 dims x 64 objs.
#define P1_THREADS 256

__global__ void __launch_bounds__(P1_THREADS) phase1_kernel(
        const float* __restrict__ q_mu, const float* __restrict__ q_var) {
    __shared__ uint16_t s_tile[32 * 66];            // [dim][obj], padded

    const int tid = threadIdx.x, tx = tid & 31, ty = tid >> 5;
    const int dt = blockIdx.x;                       // dim tile (0..127)
    const int ot = blockIdx.y;                       // obj tile (0..255)
    const size_t base = (size_t)(ot * 64 + ty) * N_DIM + dt * 32 + tx;

    float mm[8], vv[8];
    #pragma unroll
    for (int r = 0; r < 8; r++) {
        mm[r] = q_mu[base + (size_t)(r * 8) * N_DIM];
        vv[r] = q_var[base + (size_t)(r * 8) * N_DIM];
    }

    #pragma unroll
    for (int r = 0; r < 8; r++) {
        // p = 0.5*erfc(x), x = (mu/v)/sqrt2. Clamp x>=1: p(1)=0.0786 > 0.05,
        // so clamped values land in the sentinel region regardless.
        float x = __fdividef(mm[r], vv[r]) * INV_SQRT2;
        float xc = fmaxf(x, 1.0f);

        float h = xc * xc;                  // exp(-x^2), Dekker-corrected
        float l = fmaf(xc, xc, -h);
        float e = __expf(-h);
        e = fmaf(-l, e, e);

        float den = fmaf(0.3275911f, xc, 1.0f);      // A&S 7.1.26, err<=1.5e-7
        float t = __fdividef(1.0f, den);
        float poly = fmaf(t, 1.061405429f, -1.453152027f);
        poly = fmaf(t, poly, 1.421413741f);
        poly = fmaf(t, poly, -0.284496736f);
        poly = fmaf(t, poly, 0.254829592f);
        float p = 0.5f * t * poly * e;

        uint16_t bin = SENT;
        if (p <= 0.05f) {                            // thr(16383) == 0.05f
            int j = (int)ceilf(p * 327680.0f) - 1;   // thresholds uniform in p
            j = min(max(j, 0), N_OBJ - 1);
            while (j > 0 && p <= thr(j - 1)) --j;    // fp fixup, ~0-1 iters
            while (j < N_OBJ - 1 && p > thr(j)) ++j;
            bin = (uint16_t)j;
        }
        s_tile[tx * 66 + (ty + r * 8)] = bin;
    }
    __syncthreads();

    // Deterministic segment pack: warp w owns dims {w, w+8, w+16, w+24}.
    // This block is the SOLE writer of segment (d, ot): no atomics.
    // Valid bins are rank-packed at the 128B-aligned segment front.
    const int lane = tid & 31, wrp = tid >> 5;
    for (int dd = wrp; dd < 32; dd += 8) {
        const int d = dt * 32 + dd;
        uint16_t v0 = s_tile[dd * 66 + lane];
        uint16_t v1 = s_tile[dd * 66 + 32 + lane];
        unsigned m0 = __ballot_sync(0xffffffffu, v0 != SENT);
        unsigned m1 = __ballot_sync(0xffffffffu, v1 != SENT);
        int n0 = __popc(m0);
        uint16_t* dst = g_bins + (size_t)d * N_OBJ + ot * 64;
        unsigned lt = (1u << lane) - 1u;
        if (v0 != SENT) dst[__popc(m0 & lt)] = v0;
        if (v1 != SENT) dst[n0 + __popc(m1 & lt)] = v1;
        if (lane == 0)
            g_tcnt[d * OTILES + ot] = (uint8_t)(n0 + __popc(m1));
    }
}

// ---------------- phase 2: segmented histogram + bounded scan -------------
__global__ __launch_bounds__(1024, 2) void phase2_kernel(float* __restrict__ out) {
    extern __shared__ uint32_t hist[];       // up to 16384 u32 = 64 KB
    __shared__ uint32_t warp_part[32];
    __shared__ uint32_t s_carry, s_C;
    __shared__ uint32_t s_cntw[OTILES / 4];  // 64 u32 = 256 u8 counts
    __shared__ uint32_t red_cnt[32];
    __shared__ int      red_min[32];

    const int tid = threadIdx.x, lane = tid & 31, wid = tid >> 5;
    const int d = blockIdx.x;

    // counts row + C via dp4a byte-sum
    if (tid == 0) { s_C = 0; s_carry = 0; }
    __syncthreads();
    if (tid < OTILES / 4) {
        uint32_t v = ((const uint32_t*)(g_tcnt + d * OTILES))[tid];
        s_cntw[tid] = v;
        int part = __dp4a((int)v, 0x01010101, 0);
        #pragma unroll
        for (int o = 16; o > 0; o >>= 1)
            part += __shfl_down_sync(0xffffffffu, part, o);
        if (lane == 0) atomicAdd(&s_C, (uint32_t)part);
    }
    __syncthreads();

    const uint32_t C = s_C;
    if (C == 0) { if (tid == 0) out[d] = 0.0f; return; }
    const int chunks = min(16, (int)((C + 1023u) >> 10));
    const uint32_t limit = (uint32_t)chunks << 10;

    {   // vectorized zero of hist[0..limit)
        uint4* h4 = (uint4*)hist;
        uint4 z4 = {0u, 0u, 0u, 0u};
        for (int k = tid; k < (int)(limit >> 2); k += 1024) h4[k] = z4;
    }
    __syncthreads();

    // Histogram over valid elements only: warp w walks segments [8w, 8w+8).
    const uint16_t* row = g_bins + (size_t)d * N_OBJ;
    const uint8_t* cnts = (const uint8_t*)s_cntw;
    uint32_t zc = 0;                          // bin 0 hot -> aggregate
    #pragma unroll
    for (int si = 0; si < 8; si++) {
        const int s = wid * 8 + si;
        const int cnt = cnts[s];
        const uint16_t* seg = row + s * 64;
        {
            bool val = lane < cnt;
            uint32_t b = val ? (uint32_t)seg[lane] : SENT;
            if (val) { if (b == 0u) zc++; else if (b < limit) atomicAdd(&hist[b], 1u); }
        }
        if (cnt > 32) {
            int k = 32 + lane;
            bool val = k < cnt;
            uint32_t b = val ? (uint32_t)seg[k] : SENT;
            if (val) { if (b == 0u) zc++; else if (b < limit) atomicAdd(&hist[b], 1u); }
        }
    }
    #pragma unroll
    for (int o = 16; o > 0; o >>= 1) zc += __shfl_down_sync(0xffffffffu, zc, o);
    if (lane == 0 && zc) atomicAdd(&hist[0], zc);
    __syncthreads();

    // chunked inclusive scan over [0, limit): reject[j] = cum(j) >= j+1
    uint32_t count = 0;
    int firstj = 0x7fffffff;
    for (int c = 0; c < chunks; ++c) {
        int j = c * 1024 + tid;
        uint32_t x = hist[j];
        #pragma unroll
        for (int o = 1; o < 32; o <<= 1) {
            uint32_t y = __shfl_up_sync(0xffffffffu, x, o);
            if (lane >= o) x += y;
        }
        if (lane == 31) warp_part[wid] = x;
        __syncthreads();
        if (wid == 0) {
            uint32_t ww = warp_part[lane];
            #pragma unroll
            for (int o = 1; o < 32; o <<= 1) {
                uint32_t y = __shfl_up_sync(0xffffffffu, ww, o);
                if (lane >= o) ww += y;
            }
            warp_part[lane] = ww;
        }
        __syncthreads();
        uint32_t incl = x + (wid > 0 ? warp_part[wid - 1] : 0u) + s_carry;
        if (incl >= (uint32_t)(j + 1)) { count++; firstj = min(firstj, j); }
        __syncthreads();
        if (tid == 0) s_carry += warp_part[31];
        __syncthreads();
    }

    #pragma unroll
    for (int o = 16; o > 0; o >>= 1) {
        count += __shfl_down_sync(0xffffffffu, count, o);
        firstj = min(firstj, __shfl_down_sync(0xffffffffu, firstj, o));
    }
    if (lane == 0) { red_cnt[wid] = count; red_min[wid] = firstj; }
    __syncthreads();
    if (wid == 0) {
        uint32_t cc = red_cnt[lane];
        int mm = red_min[lane];
        #pragma unroll
        for (int o = 16; o > 0; o >>= 1) {
            cc += __shfl_down_sync(0xffffffffu, cc, o);
            mm = min(mm, __shfl_down_sync(0xffffffffu, mm, o));
        }
        if (lane == 0) {
            uint32_t imp = cc + ((mm == 0x7fffffff) ? 0u : (uint32_t)mm);
            out[d] = (float)imp;
        }
    }
}

extern "C" void kernel_launch(void* const* d_in, const int* in_sizes, int n_in,
                              void* d_out, int out_size) {
    const float* q_mu  = (const float*)d_in[0];
    const float* q_var = (const float*)d_in[1];
    float* out = (float*)d_out;

    cudaFuncSetAttribute((const void*)phase2_kernel,
                         cudaFuncAttributeMaxDynamicSharedMemorySize,
                         N_OBJ * (int)sizeof(uint32_t));

    dim3 g1(N_DIM / 32, N_OBJ / 64);
    phase1_kernel<<<g1, P1_THREADS>>>(q_mu, q_var);
    phase2_kernel<<<N_DIM, 1024, N_OBJ * sizeof(uint32_t)>>>(out);
}